// round 1
// baseline (speedup 1.0000x reference)
#include <cuda_runtime.h>
#include <math.h>

#define S_TOK 4032
#define DIMC  1536
#define NHEAD 12
#define HDIM  128
#define ROTC  64
#define FRAME 448

// Scratch (device globals: no allocation allowed in kernel_launch)
__device__ float g_q[S_TOK * DIMC];
__device__ float g_k[S_TOK * DIMC];
__device__ float g_v[S_TOK * DIMC];
__device__ float g_attn[S_TOK * DIMC];

// ---------------------------------------------------------------------------
// GEMM tile: C[64 x 128] block of C = A @ B + bias.
// A: [4032, 1536] row-major, B: [1536, 1536] row-major. 256 threads.
// ---------------------------------------------------------------------------
__device__ __forceinline__ void gemm_tile(const float* __restrict__ A,
                                          const float* __restrict__ B,
                                          const float* __restrict__ bias,
                                          float* __restrict__ C,
                                          int row0, int col0)
{
    __shared__ float As[16][64];    // transposed A tile: As[k][m]
    __shared__ float Bs[16][128];   // Bs[k][n]

    const int tid = threadIdx.x;
    const int ty = tid >> 4;           // 0..15
    const int tx = tid & 15;           // 0..15
    const int am = tid >> 2;           // 0..63 (A-load row)
    const int ak = (tid & 3) << 2;     // 0,4,8,12 (A-load k)

    float acc[4][8];
#pragma unroll
    for (int i = 0; i < 4; i++)
#pragma unroll
        for (int j = 0; j < 8; j++) acc[i][j] = 0.f;

    for (int kb = 0; kb < DIMC; kb += 16) {
        // Load A tile (64x16), store transposed
        float4 a4 = *(const float4*)&A[(row0 + am) * DIMC + kb + ak];
        As[ak + 0][am] = a4.x;
        As[ak + 1][am] = a4.y;
        As[ak + 2][am] = a4.z;
        As[ak + 3][am] = a4.w;
        // Load B tile (16x128)
#pragma unroll
        for (int it = 0; it < 2; it++) {
            int idx = it * 1024 + tid * 4;
            int kr = idx >> 7;
            int nn = idx & 127;
            *(float4*)&Bs[kr][nn] =
                *(const float4*)&B[(kb + kr) * DIMC + col0 + nn];
        }
        __syncthreads();
#pragma unroll
        for (int k = 0; k < 16; k++) {
            float4 av = *(const float4*)&As[k][ty * 4];
            float4 b0 = *(const float4*)&Bs[k][tx * 8];
            float4 b1 = *(const float4*)&Bs[k][tx * 8 + 4];
            float ar[4] = {av.x, av.y, av.z, av.w};
            float br[8] = {b0.x, b0.y, b0.z, b0.w, b1.x, b1.y, b1.z, b1.w};
#pragma unroll
            for (int i = 0; i < 4; i++)
#pragma unroll
                for (int j = 0; j < 8; j++) acc[i][j] += ar[i] * br[j];
        }
        __syncthreads();
    }
#pragma unroll
    for (int i = 0; i < 4; i++) {
        int r = row0 + ty * 4 + i;
#pragma unroll
        for (int j = 0; j < 8; j++) {
            int c = col0 + tx * 8 + j;
            C[r * DIMC + c] = acc[i][j] + bias[c];
        }
    }
}

// QKV projections: z selects Q/K/V
__global__ void qkv_gemm(const float* __restrict__ x,
                         const float* __restrict__ Wq, const float* __restrict__ bq,
                         const float* __restrict__ Wk, const float* __restrict__ bk,
                         const float* __restrict__ Wv, const float* __restrict__ bv)
{
    int z = blockIdx.z;
    const float* B    = (z == 0) ? Wq : ((z == 1) ? Wk : Wv);
    const float* bias = (z == 0) ? bq : ((z == 1) ? bk : bv);
    float* C          = (z == 0) ? g_q : ((z == 1) ? g_k : g_v);
    gemm_tile(x, B, bias, C, blockIdx.y * 64, blockIdx.x * 128);
}

// Output projection
__global__ void out_gemm(const float* __restrict__ Wo,
                         const float* __restrict__ bo,
                         float* __restrict__ out)
{
    gemm_tile(g_attn, Wo, bo, out, blockIdx.y * 64, blockIdx.x * 128);
}

// ---------------------------------------------------------------------------
// Fused RMSNorm (over full DIM=1536) + 3D RoPE, in-place on g_q / g_k.
// One block per token, 256 threads (3 pairs each).
// ---------------------------------------------------------------------------
__global__ void norm_rope_kernel(const float* __restrict__ freqs,
                                 const float* __restrict__ gq,
                                 const float* __restrict__ gk)
{
    int s = blockIdx.x;
    int tid = threadIdx.x;
    float* qrow = g_q + (size_t)s * DIMC;
    float* krow = g_k + (size_t)s * DIMC;

    float2 qv[3], kv[3];
    float sq = 0.f, sk = 0.f;
#pragma unroll
    for (int p = 0; p < 3; p++) {
        int pr = tid + p * 256;
        qv[p] = *(const float2*)&qrow[2 * pr];
        kv[p] = *(const float2*)&krow[2 * pr];
        sq += qv[p].x * qv[p].x + qv[p].y * qv[p].y;
        sk += kv[p].x * kv[p].x + kv[p].y * kv[p].y;
    }
    __shared__ float red[2][8];
#pragma unroll
    for (int o = 16; o > 0; o >>= 1) {
        sq += __shfl_down_sync(0xffffffffu, sq, o);
        sk += __shfl_down_sync(0xffffffffu, sk, o);
    }
    int warp = tid >> 5;
    if ((tid & 31) == 0) { red[0][warp] = sq; red[1][warp] = sk; }
    __syncthreads();
    sq = 0.f; sk = 0.f;
#pragma unroll
    for (int w = 0; w < 8; w++) { sq += red[0][w]; sk += red[1][w]; }
    float rq = rsqrtf(sq * (1.f / DIMC) + 1e-6f);
    float rk = rsqrtf(sk * (1.f / DIMC) + 1e-6f);

    int f = s / FRAME;
    int rem = s % FRAME;
    int hh = rem / 28;
    int ww = rem % 28;
#pragma unroll
    for (int p = 0; p < 3; p++) {
        int pr = tid + p * 256;
        int rot = pr & 63;    // position within head, per pair
        float a;
        if (rot < 22)       a = freqs[f  * ROTC + rot];
        else if (rot < 43)  a = freqs[hh * ROTC + rot];
        else                a = freqs[ww * ROTC + rot];
        float c = cosf(a), sn = sinf(a);
        float q0 = qv[p].x * rq * gq[2 * pr];
        float q1 = qv[p].y * rq * gq[2 * pr + 1];
        float k0 = kv[p].x * rk * gk[2 * pr];
        float k1 = kv[p].y * rk * gk[2 * pr + 1];
        float2 qo = make_float2(q0 * c - q1 * sn, q0 * sn + q1 * c);
        float2 ko = make_float2(k0 * c - k1 * sn, k0 * sn + k1 * c);
        *(float2*)&qrow[2 * pr] = qo;
        *(float2*)&krow[2 * pr] = ko;
    }
}

// ---------------------------------------------------------------------------
// Frame-causal flash attention, fp32. Block = (q-tile of 64, head).
// 448 = 7*64 so frame boundaries align with tiles: no masking needed,
// just the per-block key trip count.
// SMEM: Qt[128][64] Kt[128][64] Vs[64][128] Ss[64][65] + m/l/fac
// ---------------------------------------------------------------------------
#define ATTN_SMEM_FLOATS (8192 + 8192 + 8192 + 64 * 65 + 192)

__global__ void attn_kernel()
{
    extern __shared__ float sm[];
    float* Qt   = sm;                         // [128][64] (transposed)
    float* Kt   = sm + 8192;                  // [128][64] (transposed)
    float* Vs   = sm + 16384;                 // [64][128]
    float* Ss   = sm + 24576;                 // [64][65]
    float* mrow = sm + 24576 + 64 * 65;       // [64]
    float* lrow = mrow + 64;                  // [64]
    float* fac  = lrow + 64;                  // [64]

    const int tid = threadIdx.x;
    const int ty = tid >> 4, tx = tid & 15;
    const int row0 = blockIdx.x * 64;
    const int h = blockIdx.y;
    const int frame = row0 / FRAME;
    const int ktiles = (frame + 1) * (FRAME / 64);
    const float scale = 0.08838834764831845f;  // 1/sqrt(128)

    // Load Q tile transposed
#pragma unroll
    for (int i = 0; i < 8; i++) {
        int idx = tid + i * 256;         // 0..2047
        int r = idx >> 5;                // 0..63
        int dq = (idx & 31) << 2;        // 0..124
        float4 v = *(const float4*)&g_q[(size_t)(row0 + r) * DIMC + h * HDIM + dq];
        Qt[(dq + 0) * 64 + r] = v.x;
        Qt[(dq + 1) * 64 + r] = v.y;
        Qt[(dq + 2) * 64 + r] = v.z;
        Qt[(dq + 3) * 64 + r] = v.w;
    }
    if (tid < 64) { mrow[tid] = -1e30f; lrow[tid] = 0.f; }

    float acc[4][8];
#pragma unroll
    for (int i = 0; i < 4; i++)
#pragma unroll
        for (int j = 0; j < 8; j++) acc[i][j] = 0.f;

    for (int kt = 0; kt < ktiles; kt++) {
        int krow0 = kt * 64;
        // Load K (transposed) + V tiles
#pragma unroll
        for (int i = 0; i < 8; i++) {
            int idx = tid + i * 256;
            int r = idx >> 5;
            int dq = (idx & 31) << 2;
            float4 kvv = *(const float4*)&g_k[(size_t)(krow0 + r) * DIMC + h * HDIM + dq];
            Kt[(dq + 0) * 64 + r] = kvv.x;
            Kt[(dq + 1) * 64 + r] = kvv.y;
            Kt[(dq + 2) * 64 + r] = kvv.z;
            Kt[(dq + 3) * 64 + r] = kvv.w;
            float4 vvv = *(const float4*)&g_v[(size_t)(krow0 + r) * DIMC + h * HDIM + dq];
            *(float4*)&Vs[r * 128 + dq] = vvv;
        }
        __syncthreads();

        // Scores: S = Q K^T, thread computes 4q x 4k
        float sc[4][4];
#pragma unroll
        for (int i = 0; i < 4; i++)
#pragma unroll
            for (int j = 0; j < 4; j++) sc[i][j] = 0.f;
#pragma unroll 4
        for (int d = 0; d < 128; d++) {
            float4 q4 = *(const float4*)&Qt[d * 64 + ty * 4];
            float4 k4 = *(const float4*)&Kt[d * 64 + tx * 4];
            float qr[4] = {q4.x, q4.y, q4.z, q4.w};
            float kr[4] = {k4.x, k4.y, k4.z, k4.w};
#pragma unroll
            for (int i = 0; i < 4; i++)
#pragma unroll
                for (int j = 0; j < 4; j++) sc[i][j] += qr[i] * kr[j];
        }
#pragma unroll
        for (int i = 0; i < 4; i++)
#pragma unroll
            for (int j = 0; j < 4; j++)
                Ss[(ty * 4 + i) * 65 + tx * 4 + j] = sc[i][j] * scale;
        __syncthreads();

        // Online softmax: 4 lanes per row (64 rows x 4 = 256 threads)
        {
            int row = tid >> 2;
            int ln = tid & 3;
            float vals[16];
            float mloc = -1e30f;
#pragma unroll
            for (int j = 0; j < 16; j++) {
                vals[j] = Ss[row * 65 + ln * 16 + j];
                mloc = fmaxf(mloc, vals[j]);
            }
            mloc = fmaxf(mloc, __shfl_xor_sync(0xffffffffu, mloc, 1));
            mloc = fmaxf(mloc, __shfl_xor_sync(0xffffffffu, mloc, 2));
            float mnew = fmaxf(mrow[row], mloc);
            float sum = 0.f;
#pragma unroll
            for (int j = 0; j < 16; j++) {
                float p = __expf(vals[j] - mnew);
                Ss[row * 65 + ln * 16 + j] = p;
                sum += p;
            }
            sum += __shfl_xor_sync(0xffffffffu, sum, 1);
            sum += __shfl_xor_sync(0xffffffffu, sum, 2);
            if (ln == 0) {
                float f0 = __expf(mrow[row] - mnew);
                fac[row] = f0;
                lrow[row] = lrow[row] * f0 + sum;
                mrow[row] = mnew;
            }
        }
        __syncthreads();

        // Rescale accumulators, then O += P @ V (thread: 4q x 8d)
#pragma unroll
        for (int i = 0; i < 4; i++) {
            float f0 = fac[ty * 4 + i];
#pragma unroll
            for (int j = 0; j < 8; j++) acc[i][j] *= f0;
        }
#pragma unroll 4
        for (int kk = 0; kk < 64; kk++) {
            float4 v0 = *(const float4*)&Vs[kk * 128 + tx * 8];
            float4 v1 = *(const float4*)&Vs[kk * 128 + tx * 8 + 4];
            float vr[8] = {v0.x, v0.y, v0.z, v0.w, v1.x, v1.y, v1.z, v1.w};
            float pr[4];
#pragma unroll
            for (int i = 0; i < 4; i++) pr[i] = Ss[(ty * 4 + i) * 65 + kk];
#pragma unroll
            for (int i = 0; i < 4; i++)
#pragma unroll
                for (int j = 0; j < 8; j++) acc[i][j] += pr[i] * vr[j];
        }
        __syncthreads();
    }

    // Epilogue: normalize, write [S, H*D]
#pragma unroll
    for (int i = 0; i < 4; i++) {
        float inv = 1.f / lrow[ty * 4 + i];
        int r = row0 + ty * 4 + i;
#pragma unroll
        for (int j = 0; j < 8; j++) {
            g_attn[(size_t)r * DIMC + h * HDIM + tx * 8 + j] = acc[i][j] * inv;
        }
    }
}

// ---------------------------------------------------------------------------
extern "C" void kernel_launch(void* const* d_in, const int* in_sizes, int n_in,
                              void* d_out, int out_size)
{
    (void)in_sizes; (void)n_in; (void)out_size;
    const float* x     = (const float*)d_in[0];
    // d_in[1] = seq_lens, d_in[2] = grid_sizes : compile-time constants here
    const float* freqs = (const float*)d_in[3];
    const float* Wq    = (const float*)d_in[4];
    const float* bq    = (const float*)d_in[5];
    const float* Wk    = (const float*)d_in[6];
    const float* bk    = (const float*)d_in[7];
    const float* Wv    = (const float*)d_in[8];
    const float* bv    = (const float*)d_in[9];
    const float* Wo    = (const float*)d_in[10];
    const float* bo    = (const float*)d_in[11];
    const float* gq    = (const float*)d_in[12];
    const float* gk    = (const float*)d_in[13];
    float* out = (float*)d_out;

    const int smem_bytes = ATTN_SMEM_FLOATS * 4;  // 115,712 B
    cudaFuncSetAttribute(attn_kernel,
                         cudaFuncAttributeMaxDynamicSharedMemorySize, smem_bytes);

    qkv_gemm<<<dim3(12, 63, 3), 256>>>(x, Wq, bq, Wk, bk, Wv, bv);
    norm_rope_kernel<<<S_TOK, 256>>>(freqs, gq, gk);
    attn_kernel<<<dim3(63, 12), 256, smem_bytes>>>();
    out_gemm<<<dim3(12, 63), 256>>>(Wo, bo, out);
}

// round 2
// speedup vs baseline: 4.2935x; 4.2935x over previous
#include <cuda_runtime.h>
#include <math.h>

#define S_TOK 4032
#define DIMC  1536
#define NHEAD 12
#define HDIM  128
#define ROTC  64
#define FRAME 448

// Scratch (device globals: no allocation allowed in kernel_launch)
__device__ float g_q[S_TOK * DIMC];
__device__ float g_k[S_TOK * DIMC];
__device__ float g_v[S_TOK * DIMC];
__device__ float g_attn[S_TOK * DIMC];

// ---------------------------------------------------------------------------
// tf32 helpers
// ---------------------------------------------------------------------------
__device__ __forceinline__ unsigned f2tf(float x) {
    unsigned r;
    asm("cvt.rna.tf32.f32 %0, %1;" : "=r"(r) : "f"(x));
    return r;
}
__device__ __forceinline__ uint4 cvt4(float4 v) {
    uint4 t;
    t.x = f2tf(v.x); t.y = f2tf(v.y); t.z = f2tf(v.z); t.w = f2tf(v.w);
    return t;
}
__device__ __forceinline__ void mma_tf32(float* d, const unsigned* a,
                                         unsigned b0, unsigned b1) {
    asm volatile(
        "mma.sync.aligned.m16n8k8.row.col.f32.tf32.tf32.f32 "
        "{%0,%1,%2,%3}, {%4,%5,%6,%7}, {%8,%9}, {%0,%1,%2,%3};\n"
        : "+f"(d[0]), "+f"(d[1]), "+f"(d[2]), "+f"(d[3])
        : "r"(a[0]), "r"(a[1]), "r"(a[2]), "r"(a[3]), "r"(b0), "r"(b1));
}

// ---------------------------------------------------------------------------
// tf32 tensor-core GEMM: C[4032,1536] = A[4032,1536] @ B[1536,1536] + bias
// CTA tile 128x128, K-step 32. 256 threads = 8 warps (2m x 4n), warp 64x32.
// ---------------------------------------------------------------------------
#define AS_STRIDE 133
#define BS_STRIDE 132

__device__ __forceinline__ void gemm_tc(const float* __restrict__ A,
                                        const float* __restrict__ B,
                                        const float* __restrict__ bias,
                                        float* __restrict__ C,
                                        int row0, int col0)
{
    __shared__ unsigned As_u[32 * AS_STRIDE];   // [k][m] transposed
    __shared__ unsigned Bs_u[32 * BS_STRIDE];   // [k][n]

    const int tid  = threadIdx.x;
    const int lane = tid & 31;
    const int warp = tid >> 5;
    const int wm = warp >> 2;       // 0..1
    const int wn = warp & 3;        // 0..3
    const int r  = lane >> 2;       // 0..7
    const int c  = lane & 3;        // 0..3

    // staging coords
    const int ar  = tid >> 3;            // 0..31 (A row within pass)
    const int akk = (tid & 7) << 2;      // 0,4,..,28 (A k within block)
    const int br  = warp;                // 0..7 (B k-row within pass)
    const int bn4 = (tid & 31) << 2;     // 0..124 (B col)

    float acc[4][4][4];
#pragma unroll
    for (int mt = 0; mt < 4; mt++)
#pragma unroll
        for (int nt = 0; nt < 4; nt++)
#pragma unroll
            for (int i = 0; i < 4; i++) acc[mt][nt][i] = 0.f;

    for (int kb = 0; kb < DIMC; kb += 32) {
        __syncthreads();
        // Stage A (128 rows x 32 k), transposed to [k][m], tf32
#pragma unroll
        for (int p = 0; p < 4; p++) {
            int row = row0 + p * 32 + ar;
            row = (row < S_TOK) ? row : (S_TOK - 1);
            float4 v = *(const float4*)&A[(size_t)row * DIMC + kb + akk];
            As_u[(akk + 0) * AS_STRIDE + p * 32 + ar] = f2tf(v.x);
            As_u[(akk + 1) * AS_STRIDE + p * 32 + ar] = f2tf(v.y);
            As_u[(akk + 2) * AS_STRIDE + p * 32 + ar] = f2tf(v.z);
            As_u[(akk + 3) * AS_STRIDE + p * 32 + ar] = f2tf(v.w);
        }
        // Stage B (32 k x 128 n), tf32
#pragma unroll
        for (int p = 0; p < 4; p++) {
            int krow = kb + p * 8 + br;
            float4 v = *(const float4*)&B[(size_t)krow * DIMC + col0 + bn4];
            *(uint4*)&Bs_u[(p * 8 + br) * BS_STRIDE + bn4] = cvt4(v);
        }
        __syncthreads();

#pragma unroll
        for (int kk = 0; kk < 32; kk += 8) {
            unsigned a[4][4];
#pragma unroll
            for (int mt = 0; mt < 4; mt++) {
                int mb = wm * 64 + mt * 16;
                a[mt][0] = As_u[(kk + c) * AS_STRIDE + mb + r];
                a[mt][1] = As_u[(kk + c) * AS_STRIDE + mb + r + 8];
                a[mt][2] = As_u[(kk + c + 4) * AS_STRIDE + mb + r];
                a[mt][3] = As_u[(kk + c + 4) * AS_STRIDE + mb + r + 8];
            }
            unsigned b[4][2];
#pragma unroll
            for (int nt = 0; nt < 4; nt++) {
                int nb = wn * 32 + nt * 8;
                b[nt][0] = Bs_u[(kk + c) * BS_STRIDE + nb + r];
                b[nt][1] = Bs_u[(kk + c + 4) * BS_STRIDE + nb + r];
            }
#pragma unroll
            for (int mt = 0; mt < 4; mt++)
#pragma unroll
                for (int nt = 0; nt < 4; nt++)
                    mma_tf32(acc[mt][nt], a[mt], b[nt][0], b[nt][1]);
        }
    }

    // Epilogue
#pragma unroll
    for (int mt = 0; mt < 4; mt++) {
        int row_a = row0 + wm * 64 + mt * 16 + r;
        int row_b = row_a + 8;
#pragma unroll
        for (int nt = 0; nt < 4; nt++) {
            int col = col0 + wn * 32 + nt * 8 + 2 * c;
            float b0 = bias[col], b1 = bias[col + 1];
            if (row_a < S_TOK) {
                float2 v0 = make_float2(acc[mt][nt][0] + b0, acc[mt][nt][1] + b1);
                *(float2*)&C[(size_t)row_a * DIMC + col] = v0;
            }
            if (row_b < S_TOK) {
                float2 v1 = make_float2(acc[mt][nt][2] + b0, acc[mt][nt][3] + b1);
                *(float2*)&C[(size_t)row_b * DIMC + col] = v1;
            }
        }
    }
}

__global__ void __launch_bounds__(256)
qkv_gemm(const float* __restrict__ x,
         const float* __restrict__ Wq, const float* __restrict__ bq,
         const float* __restrict__ Wk, const float* __restrict__ bk,
         const float* __restrict__ Wv, const float* __restrict__ bv)
{
    int z = blockIdx.z;
    const float* B    = (z == 0) ? Wq : ((z == 1) ? Wk : Wv);
    const float* bias = (z == 0) ? bq : ((z == 1) ? bk : bv);
    float* C          = (z == 0) ? g_q : ((z == 1) ? g_k : g_v);
    gemm_tc(x, B, bias, C, blockIdx.y * 128, blockIdx.x * 128);
}

__global__ void __launch_bounds__(256)
out_gemm(const float* __restrict__ Wo, const float* __restrict__ bo,
         float* __restrict__ out)
{
    gemm_tc(g_attn, Wo, bo, out, blockIdx.y * 128, blockIdx.x * 128);
}

// ---------------------------------------------------------------------------
// Fused RMSNorm (full DIM) + 3D RoPE, in-place on g_q / g_k. 1 block/token.
// ---------------------------------------------------------------------------
__global__ void norm_rope_kernel(const float* __restrict__ freqs,
                                 const float* __restrict__ gq,
                                 const float* __restrict__ gk)
{
    int s = blockIdx.x;
    int tid = threadIdx.x;
    float* qrow = g_q + (size_t)s * DIMC;
    float* krow = g_k + (size_t)s * DIMC;

    float2 qv[3], kv[3];
    float sq = 0.f, sk = 0.f;
#pragma unroll
    for (int p = 0; p < 3; p++) {
        int pr = tid + p * 256;
        qv[p] = *(const float2*)&qrow[2 * pr];
        kv[p] = *(const float2*)&krow[2 * pr];
        sq += qv[p].x * qv[p].x + qv[p].y * qv[p].y;
        sk += kv[p].x * kv[p].x + kv[p].y * kv[p].y;
    }
    __shared__ float red[2][8];
#pragma unroll
    for (int o = 16; o > 0; o >>= 1) {
        sq += __shfl_down_sync(0xffffffffu, sq, o);
        sk += __shfl_down_sync(0xffffffffu, sk, o);
    }
    int warp = tid >> 5;
    if ((tid & 31) == 0) { red[0][warp] = sq; red[1][warp] = sk; }
    __syncthreads();
    sq = 0.f; sk = 0.f;
#pragma unroll
    for (int w = 0; w < 8; w++) { sq += red[0][w]; sk += red[1][w]; }
    float rq = rsqrtf(sq * (1.f / DIMC) + 1e-6f);
    float rk = rsqrtf(sk * (1.f / DIMC) + 1e-6f);

    int f = s / FRAME;
    int rem = s % FRAME;
    int hh = rem / 28;
    int ww = rem % 28;
#pragma unroll
    for (int p = 0; p < 3; p++) {
        int pr = tid + p * 256;
        int rot = pr & 63;
        float a;
        if (rot < 22)       a = freqs[f  * ROTC + rot];
        else if (rot < 43)  a = freqs[hh * ROTC + rot];
        else                a = freqs[ww * ROTC + rot];
        float cc = cosf(a), sn = sinf(a);
        float q0 = qv[p].x * rq * gq[2 * pr];
        float q1 = qv[p].y * rq * gq[2 * pr + 1];
        float k0 = kv[p].x * rk * gk[2 * pr];
        float k1 = kv[p].y * rk * gk[2 * pr + 1];
        *(float2*)&qrow[2 * pr] = make_float2(q0 * cc - q1 * sn, q0 * sn + q1 * cc);
        *(float2*)&krow[2 * pr] = make_float2(k0 * cc - k1 * sn, k0 * sn + k1 * cc);
    }
}

// ---------------------------------------------------------------------------
// Frame-causal flash attention, tf32 tensor cores.
// Block = (64 q-rows, head), 128 threads (4 warps, 16 q-rows each).
// smem: Qs[64][132] (reused as Ps[64][68]), Ks[64][132], Vs[64][132] (tf32)
// ---------------------------------------------------------------------------
#define QS_OFF 0
#define KS_OFF (64 * 132)
#define VS_OFF (128 * 132)
#define ATTN_SMEM_U (192 * 132)
#define PS_STRIDE 68

__global__ void __launch_bounds__(128)
attn_kernel()
{
    extern __shared__ unsigned smu[];
    unsigned* Qs = smu + QS_OFF;
    unsigned* Ps = smu + QS_OFF;    // alias (Qs dead after frag load)
    unsigned* Ks = smu + KS_OFF;
    unsigned* Vs = smu + VS_OFF;

    const int tid  = threadIdx.x;
    const int lane = tid & 31;
    const int w    = tid >> 5;         // warp 0..3
    const int r    = lane >> 2;        // 0..7
    const int c    = lane & 3;         // 0..3
    const int w16  = w * 16;

    const int row0 = blockIdx.x * 64;
    const int h    = blockIdx.y;
    const int ktiles = (row0 / FRAME + 1) * (FRAME / 64);
    const float scale = 0.08838834764831845f;   // 1/sqrt(128)

    // Stage Q (scale folded), tf32
#pragma unroll
    for (int it = 0; it < 16; it++) {
        int idx = tid + it * 128;
        int rr = idx >> 5;
        int cc = (idx & 31) << 2;
        float4 v = *(const float4*)&g_q[(size_t)(row0 + rr) * DIMC + h * HDIM + cc];
        v.x *= scale; v.y *= scale; v.z *= scale; v.w *= scale;
        *(uint4*)&Qs[rr * 132 + cc] = cvt4(v);
    }
    __syncthreads();

    // Q fragments (held in registers for the whole block)
    unsigned qa[16][4];
#pragma unroll
    for (int dt = 0; dt < 16; dt++) {
        qa[dt][0] = Qs[(w16 + r) * 132 + dt * 8 + c];
        qa[dt][1] = Qs[(w16 + r + 8) * 132 + dt * 8 + c];
        qa[dt][2] = Qs[(w16 + r) * 132 + dt * 8 + c + 4];
        qa[dt][3] = Qs[(w16 + r + 8) * 132 + dt * 8 + c + 4];
    }

    float O[16][4];
#pragma unroll
    for (int nt = 0; nt < 16; nt++)
#pragma unroll
        for (int i = 0; i < 4; i++) O[nt][i] = 0.f;
    float m0 = -1e30f, m1 = -1e30f, l0 = 0.f, l1 = 0.f;

    for (int kt = 0; kt < ktiles; kt++) {
        int krow0 = kt * 64;
        __syncthreads();   // protect Ks/Vs from previous iteration readers
        // Stage K, V (tf32)
#pragma unroll
        for (int it = 0; it < 16; it++) {
            int idx = tid + it * 128;
            int rr = idx >> 5;
            int cc = (idx & 31) << 2;
            float4 kv = *(const float4*)&g_k[(size_t)(krow0 + rr) * DIMC + h * HDIM + cc];
            *(uint4*)&Ks[rr * 132 + cc] = cvt4(kv);
            float4 vv = *(const float4*)&g_v[(size_t)(krow0 + rr) * DIMC + h * HDIM + cc];
            *(uint4*)&Vs[rr * 132 + cc] = cvt4(vv);
        }
        __syncthreads();

        // S = Q K^T  (warp's 16 q-rows x 64 keys)
        float S[8][4];
#pragma unroll
        for (int nt = 0; nt < 8; nt++)
#pragma unroll
            for (int i = 0; i < 4; i++) S[nt][i] = 0.f;
#pragma unroll
        for (int dt = 0; dt < 16; dt++) {
#pragma unroll
            for (int nt = 0; nt < 8; nt++) {
                unsigned b0 = Ks[(nt * 8 + r) * 132 + dt * 8 + c];
                unsigned b1 = Ks[(nt * 8 + r) * 132 + dt * 8 + c + 4];
                mma_tf32(S[nt], qa[dt], b0, b1);
            }
        }

        // Online softmax (rows r and r+8 of the warp band)
        float mx0 = -1e30f, mx1 = -1e30f;
#pragma unroll
        for (int nt = 0; nt < 8; nt++) {
            mx0 = fmaxf(mx0, fmaxf(S[nt][0], S[nt][1]));
            mx1 = fmaxf(mx1, fmaxf(S[nt][2], S[nt][3]));
        }
        mx0 = fmaxf(mx0, __shfl_xor_sync(0xffffffffu, mx0, 1));
        mx0 = fmaxf(mx0, __shfl_xor_sync(0xffffffffu, mx0, 2));
        mx1 = fmaxf(mx1, __shfl_xor_sync(0xffffffffu, mx1, 1));
        mx1 = fmaxf(mx1, __shfl_xor_sync(0xffffffffu, mx1, 2));
        float mn0 = fmaxf(m0, mx0), mn1 = fmaxf(m1, mx1);
        float fac0 = __expf(m0 - mn0), fac1 = __expf(m1 - mn1);

        __syncwarp();   // previous PV reads of Ps done before overwrite
        float sum0 = 0.f, sum1 = 0.f;
#pragma unroll
        for (int nt = 0; nt < 8; nt++) {
            float p00 = __expf(S[nt][0] - mn0);
            float p01 = __expf(S[nt][1] - mn0);
            float p10 = __expf(S[nt][2] - mn1);
            float p11 = __expf(S[nt][3] - mn1);
            sum0 += p00 + p01;
            sum1 += p10 + p11;
            uint2 u0 = make_uint2(f2tf(p00), f2tf(p01));
            uint2 u1 = make_uint2(f2tf(p10), f2tf(p11));
            *(uint2*)&Ps[(w16 + r) * PS_STRIDE + nt * 8 + 2 * c] = u0;
            *(uint2*)&Ps[(w16 + r + 8) * PS_STRIDE + nt * 8 + 2 * c] = u1;
        }
        sum0 += __shfl_xor_sync(0xffffffffu, sum0, 1);
        sum0 += __shfl_xor_sync(0xffffffffu, sum0, 2);
        sum1 += __shfl_xor_sync(0xffffffffu, sum1, 1);
        sum1 += __shfl_xor_sync(0xffffffffu, sum1, 2);
        l0 = l0 * fac0 + sum0;
        l1 = l1 * fac1 + sum1;
        m0 = mn0; m1 = mn1;

        // Rescale O
#pragma unroll
        for (int nt = 0; nt < 16; nt++) {
            O[nt][0] *= fac0; O[nt][1] *= fac0;
            O[nt][2] *= fac1; O[nt][3] *= fac1;
        }
        __syncwarp();   // Ps visible to all lanes of the warp

        // O += P V
#pragma unroll
        for (int k8 = 0; k8 < 8; k8++) {
            unsigned pa[4];
            pa[0] = Ps[(w16 + r) * PS_STRIDE + k8 * 8 + c];
            pa[1] = Ps[(w16 + r + 8) * PS_STRIDE + k8 * 8 + c];
            pa[2] = Ps[(w16 + r) * PS_STRIDE + k8 * 8 + c + 4];
            pa[3] = Ps[(w16 + r + 8) * PS_STRIDE + k8 * 8 + c + 4];
#pragma unroll
            for (int nt = 0; nt < 16; nt++) {
                unsigned b0 = Vs[(k8 * 8 + c) * 132 + nt * 8 + r];
                unsigned b1 = Vs[(k8 * 8 + c + 4) * 132 + nt * 8 + r];
                mma_tf32(O[nt], pa, b0, b1);
            }
        }
    }

    // Epilogue: normalize, write [S, H*D]
    float inv0 = 1.f / l0, inv1 = 1.f / l1;
    int row_a = row0 + w16 + r;
    int row_b = row_a + 8;
#pragma unroll
    for (int nt = 0; nt < 16; nt++) {
        int col = h * HDIM + nt * 8 + 2 * c;
        *(float2*)&g_attn[(size_t)row_a * DIMC + col] =
            make_float2(O[nt][0] * inv0, O[nt][1] * inv0);
        *(float2*)&g_attn[(size_t)row_b * DIMC + col] =
            make_float2(O[nt][2] * inv1, O[nt][3] * inv1);
    }
}

// ---------------------------------------------------------------------------
extern "C" void kernel_launch(void* const* d_in, const int* in_sizes, int n_in,
                              void* d_out, int out_size)
{
    (void)in_sizes; (void)n_in; (void)out_size;
    const float* x     = (const float*)d_in[0];
    const float* freqs = (const float*)d_in[3];
    const float* Wq    = (const float*)d_in[4];
    const float* bq    = (const float*)d_in[5];
    const float* Wk    = (const float*)d_in[6];
    const float* bk    = (const float*)d_in[7];
    const float* Wv    = (const float*)d_in[8];
    const float* bv    = (const float*)d_in[9];
    const float* Wo    = (const float*)d_in[10];
    const float* bo    = (const float*)d_in[11];
    const float* gq    = (const float*)d_in[12];
    const float* gk    = (const float*)d_in[13];
    float* out = (float*)d_out;

    const int attn_smem = ATTN_SMEM_U * 4;   // 101,376 B
    cudaFuncSetAttribute(attn_kernel,
                         cudaFuncAttributeMaxDynamicSharedMemorySize, attn_smem);

    qkv_gemm<<<dim3(12, 32, 3), 256>>>(x, Wq, bq, Wk, bk, Wv, bv);
    norm_rope_kernel<<<S_TOK, 256>>>(freqs, gq, gk);
    attn_kernel<<<dim3(63, 12), 128, attn_smem>>>();
    out_gemm<<<dim3(12, 32), 256>>>(Wo, bo, out);
}